// round 15
// baseline (speedup 1.0000x reference)
#include <cuda_runtime.h>

#define BATCH 4
#define KTGT  64
#define L     4                 // landmarks per thread (2 f32x2 pairs)
#define TPB   64                // quarter-size CTAs: finer quantum, cheap barriers
#define TILE  (TPB * L)         // 256

typedef unsigned long long u64;

// ------------- statically-initialized device scratch (no allocs) ----------
#define I8  0x7f800000u,0x7f800000u,0x7f800000u,0x7f800000u,0x7f800000u,0x7f800000u,0x7f800000u,0x7f800000u
#define I64 I8,I8,I8,I8,I8,I8,I8,I8
__device__ unsigned g_g2p[BATCH * KTGT] = { I64, I64, I64, I64 }; // +inf bits
__device__ int      g_cnt[BATCH];
__device__ float    g_dist[BATCH], g_p2g[BATCH], g_sep[BATCH];
__device__ unsigned g_ticket;                                      // zero-init

// ------------- f32x2 packed-math helpers (Blackwell FFMA2 path) -----------
__device__ __forceinline__ u64 pk2(float a, float b) {
    u64 d; asm("mov.b64 %0, {%1, %2};" : "=l"(d) : "f"(a), "f"(b)); return d;
}
__device__ __forceinline__ void upk2(float& a, float& b, u64 d) {
    asm("mov.b64 {%0, %1}, %2;" : "=f"(a), "=f"(b) : "l"(d));
}
__device__ __forceinline__ u64 add2(u64 a, u64 b) {
    u64 d; asm("add.rn.f32x2 %0, %1, %2;" : "=l"(d) : "l"(a), "l"(b)); return d;
}
__device__ __forceinline__ u64 fma2(u64 a, u64 b, u64 c) {
    u64 d; asm("fma.rn.f32x2 %0, %1, %2, %3;" : "=l"(d) : "l"(a), "l"(b), "l"(c)); return d;
}
__device__ __forceinline__ float half_of(u64 d, int h) {
    float a, b; upk2(a, b, d); return h ? b : a;
}

struct __align__(16) Smem {
    u64      s_tp[KTGT * 4];   // (-2tx,-2ty,-2tz,|t|^2) duplicated f32x2
    float    s_d0[TPB * L];
    float    s_red[6];         // 3 sums x 2 warps
    float    s_fin[BATCH];
    int      s_cnt;
    unsigned s_last;
};

// ---------------- persistent fused kernel (R14 loop, TPB=64) ---------------
__global__ void __launch_bounds__(TPB, 16) k_main(
    const float* __restrict__ lC, const float* __restrict__ lF,
    const float* __restrict__ tC, const int* __restrict__ tF,
    const int* __restrict__ classes, int nclass, int N, int ntx,
    float* __restrict__ out)
{
    __shared__ Smem sm;
    const int tid  = threadIdx.x;
    const int lane = tid & 31;
    const int ntiles = ntx * BATCH;

    for (int tile = blockIdx.x; tile < ntiles; tile += gridDim.x) {
        const int b    = tile / ntx;
        const int base = (tile - b * ntx) * TILE;

        __syncthreads();   // previous tile fully consumed smem

        // ---- landmark loads + P-form precompute (LDGs overlap compaction)
        u64 cx2[2], cy2[2], cz2[2], c22[2], px2[2], py2[2], pz2[2], p22[2];
        #pragma unroll
        for (int p = 0; p < 2; p++) {
            float cc[2][3], pp[2][3], c2h[2], p2h[2];
            #pragma unroll
            for (int h = 0; h < 2; h++) {
                int i = 2 * p + h;
                int n = base + tid + i * TPB;
                float d0v = 0.f;
                if (n < N) {
                    const float* pc = lC + ((size_t)b * N + n) * 3;
                    cc[h][0] = pc[0]; cc[h][1] = pc[1]; cc[h][2] = pc[2];
                    float4 f = reinterpret_cast<const float4*>(lF)[(size_t)b * N + n];
                    d0v = f.x;
                    pp[h][0] = cc[h][0] + f.y;
                    pp[h][1] = cc[h][1] + f.z;
                    pp[h][2] = cc[h][2] + f.w;
                } else {
                    cc[h][0] = 1e18f; cc[h][1] = 0.f; cc[h][2] = 0.f;
                    pp[h][0] = 1e18f; pp[h][1] = 0.f; pp[h][2] = 0.f;
                }
                sm.s_d0[tid + i * TPB] = d0v;
                c2h[h] = fmaf(cc[h][0], cc[h][0], fmaf(cc[h][1], cc[h][1], cc[h][2] * cc[h][2]));
                p2h[h] = fmaf(pp[h][0], pp[h][0], fmaf(pp[h][1], pp[h][1], pp[h][2] * pp[h][2]));
            }
            cx2[p] = pk2(cc[0][0], cc[1][0]);
            cy2[p] = pk2(cc[0][1], cc[1][1]);
            cz2[p] = pk2(cc[0][2], cc[1][2]);
            c22[p] = pk2(c2h[0],   c2h[1]);
            px2[p] = pk2(pp[0][0], pp[1][0]);
            py2[p] = pk2(pp[0][1], pp[1][1]);
            pz2[p] = pk2(pp[0][2], pp[1][2]);
            p22[p] = pk2(p2h[0],   p2h[1]);
        }

        // ---- per-tile target compaction (warp 0): (-2t, |t|^2) duplicated
        if (tid < 32) {
            int cnt = 0;
            #pragma unroll
            for (int half = 0; half < 2; half++) {
                int k = lane + 32 * half;
                int c = tF[b * KTGT + k];
                bool m = false;
                for (int j = 0; j < nclass; j++) m |= (c == __ldg(&classes[j]));
                unsigned bal = __ballot_sync(0xffffffffu, m);
                int pos = cnt + __popc(bal & ((1u << lane) - 1u));
                if (m) {
                    const float* p = tC + (b * KTGT + k) * 3;
                    float x = p[0], y = p[1], z = p[2];
                    float t2 = fmaf(x, x, fmaf(y, y, z * z));
                    sm.s_tp[pos * 4 + 0] = pk2(-2.f * x, -2.f * x);
                    sm.s_tp[pos * 4 + 1] = pk2(-2.f * y, -2.f * y);
                    sm.s_tp[pos * 4 + 2] = pk2(-2.f * z, -2.f * z);
                    sm.s_tp[pos * 4 + 3] = pk2(t2, t2);
                }
                cnt += __popc(bal);
            }
            if (lane == 0) { sm.s_cnt = cnt; g_cnt[b] = cnt; }
        }
        __syncthreads();
        const int cnt = sm.s_cnt;

        // ---- trackers (identical to R14)
        unsigned bk[L], sk[L];
        float    lmin[L];
        #pragma unroll
        for (int i = 0; i < L; i++) { bk[i] = 0xFFFFFFFFu; sk[i] = 0xFFFFFFFFu; lmin[i] = 3e38f; }
        unsigned r0 = 0x7f800000u, r1 = 0x7f800000u;

        auto body = [&](int k) -> unsigned {
            const ulonglong2* tp = reinterpret_cast<const ulonglong2*>(sm.s_tp + k * 4);
            ulonglong2 tA = tp[0];            // .x=-2tx .y=-2ty
            ulonglong2 tB = tp[1];            // .x=-2tz .y=|t|^2
            float m4a, m4b;
            #pragma unroll
            for (int p = 0; p < 2; p++) {
                u64 pd2 = fma2(cx2[p], tA.x, fma2(cy2[p], tA.y,
                          fma2(cz2[p], tB.x, add2(c22[p], tB.y))));
                u64 l2  = fma2(px2[p], tA.x, fma2(py2[p], tA.y,
                          fma2(pz2[p], tB.x, add2(p22[p], tB.y))));
                float pa, pb, la, lb;
                upk2(pa, pb, pd2);
                upk2(la, lb, l2);
                lmin[2*p]   = fminf(lmin[2*p],   la);
                lmin[2*p+1] = fminf(lmin[2*p+1], lb);
                float mm = fminf(la, lb);
                if (p == 0) m4a = mm; else m4b = mm;
                unsigned ka = (__float_as_uint(pa) & 0xFFFFFFC0u) | (unsigned)k;
                unsigned kb = (__float_as_uint(pb) & 0xFFFFFFC0u) | (unsigned)k;
                unsigned ta = max(ka, bk[2*p]);
                sk[2*p]   = min(sk[2*p], ta);
                bk[2*p]   = min(bk[2*p], ka);
                unsigned tb = max(kb, bk[2*p+1]);
                sk[2*p+1] = min(sk[2*p+1], tb);
                bk[2*p+1] = min(bk[2*p+1], kb);
            }
            return __reduce_min_sync(0xffffffffu, __float_as_uint(fminf(m4a, m4b)));
        };

        // REDUX consumption delayed one iteration to hide latency
        int kend0 = (cnt < 32) ? cnt : 32;
        {
            unsigned rp = 0; int kp = 99;
            #pragma unroll 4
            for (int k = 0; k < kend0; k++) {
                unsigned red = body(k);
                if (lane == kp) r0 = min(r0, rp);
                rp = red; kp = k;
            }
            if (lane == kp) r0 = min(r0, rp);
        }
        {
            unsigned rp = 0; int kp = 99;
            #pragma unroll 4
            for (int k = kend0; k < cnt; k++) {
                unsigned red = body(k);
                if (lane == kp) r1 = min(r1, rp);
                rp = red; kp = k - 32;
            }
            if (lane == kp) r1 = min(r1, rp);
        }

        // per-warp g2p mins straight to global (return unused -> REDG)
        atomicMin(&g_g2p[b * KTGT + lane],      r0);
        atomicMin(&g_g2p[b * KTGT + 32 + lane], r1);

        // ---- post-loop per-landmark terms
        auto ld2_at = [&](int i, int kk) -> float {
            int p = i >> 1, h = i & 1;
            float ntx_ = half_of(sm.s_tp[kk * 4 + 0], 0);
            float nty_ = half_of(sm.s_tp[kk * 4 + 1], 0);
            float ntz_ = half_of(sm.s_tp[kk * 4 + 2], 0);
            float tt2  = half_of(sm.s_tp[kk * 4 + 3], 0);
            float l = fmaf(half_of(px2[p], h), ntx_,
                      fmaf(half_of(py2[p], h), nty_,
                      fmaf(half_of(pz2[p], h), ntz_, half_of(p22[p], h) + tt2)));
            return fmaxf(l, 0.f);
        };

        float dl = 0.f, p2g2 = 0.f, sep = 0.f;
        #pragma unroll
        for (int i = 0; i < L; i++) {
            bool  valid = (base + tid + i * TPB) < N;
            float d0v   = sm.s_d0[tid + i * TPB];
            float pd2b  = __uint_as_float(bk[i] & 0xFFFFFFC0u);
            float mind  = sqrtf(pd2b);               // huge if cnt==0 -> fminf picks 0.2
            bool  pm    = mind < 0.1f;
            float tgt   = fminf(mind, 0.2f);
            float diff  = d0v - tgt;
            float ad    = fabsf(diff);
            float h     = (ad < 1.f) ? 0.5f * diff * diff : (ad - 0.5f);
            dl += valid ? h : 0.f;
            if (pm) {
                float l1 = ld2_at(i, (int)(bk[i] & 63u));
                float l2 = ld2_at(i, (int)(sk[i] & 63u));
                p2g2 += fmaxf(lmin[i], 0.f);
                sep  += sqrtf(__fdividef(l1, l2));
            }
        }

        #pragma unroll
        for (int o = 16; o > 0; o >>= 1) {
            dl   += __shfl_down_sync(0xffffffffu, dl,   o);
            p2g2 += __shfl_down_sync(0xffffffffu, p2g2, o);
            sep  += __shfl_down_sync(0xffffffffu, sep,  o);
        }
        int wid = tid >> 5;                          // 0..1
        if (lane == 0) { sm.s_red[wid] = dl; sm.s_red[2 + wid] = p2g2; sm.s_red[4 + wid] = sep; }
        __syncthreads();
        if (tid == 0) {
            atomicAdd(&g_dist[b], sm.s_red[0] + sm.s_red[1]);
            atomicAdd(&g_p2g[b],  sm.s_red[2] + sm.s_red[3]);
            atomicAdd(&g_sep[b],  sm.s_red[4] + sm.s_red[5]);
        }
    }

    // ---- last-block finalize + restore pristine scratch for next replay
    __threadfence();
    if (tid == 0) sm.s_last = atomicAdd(&g_ticket, 1u);
    __syncthreads();
    if (sm.s_last == gridDim.x - 1u) {
        // thread tid sums 4 consecutive g2p entries (all within one batch:
        // 64 entries/batch = 16 threads x 4), then 16-wide segmented shfl sum.
        int bb = tid >> 4;                           // batch for this 16-thread group
        int cb = g_cnt[bb];
        float v = 0.f;
        #pragma unroll
        for (int j = 0; j < 4; j++) {
            int e = tid * 4 + j;                     // global entry
            int kk = e & 63;
            v += (kk < cb) ? __uint_as_float(g_g2p[e]) : 0.f;
        }
        #pragma unroll
        for (int o = 8; o > 0; o >>= 1) v += __shfl_down_sync(0xffffffffu, v, o, 16);
        if ((tid & 15) == 0) sm.s_fin[bb] = v;
        __syncthreads();
        if (tid == 0) {
            float acc = 0.f;
            #pragma unroll
            for (int b2 = 0; b2 < BATCH; b2++) {
                acc += 0.05f * g_dist[b2]
                     + 0.05f * (g_p2g[b2] + sm.s_fin[b2])
                     + 0.0005f * ((g_cnt[b2] >= 2) ? g_sep[b2] : 0.f);
                g_dist[b2] = 0.f; g_p2g[b2] = 0.f; g_sep[b2] = 0.f;
            }
            out[0] = acc * (1.f / BATCH);
            g_ticket = 0;
        }
        #pragma unroll
        for (int j = 0; j < 4; j++)                  // restore all 256 entries
            g_g2p[tid * 4 + j] = 0x7f800000u;
    }
}

// ---------------- launch ---------------------------------------------------
extern "C" void kernel_launch(void* const* d_in, const int* in_sizes, int n_in,
                              void* d_out, int out_size)
{
    const float* lC      = (const float*)d_in[0];
    const float* lF      = (const float*)d_in[1];
    const float* tC      = (const float*)d_in[2];
    const int*   tF      = (const int*)d_in[3];
    const int*   classes = (const int*)d_in[4];
    int nclass = in_sizes[4];
    int N      = in_sizes[0] / (BATCH * 3);
    int ntx    = (N + TILE - 1) / TILE;
    int ntiles = ntx * BATCH;

    // capture-time host queries (no stream work, graph-legal)
    int dev = 0; cudaGetDevice(&dev);
    int sms = 148;
    cudaDeviceGetAttribute(&sms, cudaDevAttrMultiProcessorCount, dev);
    int bps = 0;
    cudaOccupancyMaxActiveBlocksPerMultiprocessor(&bps, k_main, TPB, 0);
    if (bps < 1) bps = 1;
    int grid = sms * bps;
    if (grid > ntiles) grid = ntiles;

    k_main<<<grid, TPB>>>(lC, lF, tC, tF, classes, nclass, N, ntx, (float*)d_out);
}

// round 16
// speedup vs baseline: 1.4558x; 1.4558x over previous
#include <cuda_runtime.h>

#define BATCH 4
#define KTGT  64
#define L     4                 // landmarks per thread (2 f32x2 pairs)
#define TPB   128               // validated optimum (R14)
#define TILE  (TPB * L)         // 512

typedef unsigned long long u64;

// ------------- statically-initialized device scratch (no allocs) ----------
#define I8  0x7f800000u,0x7f800000u,0x7f800000u,0x7f800000u,0x7f800000u,0x7f800000u,0x7f800000u,0x7f800000u
#define I64 I8,I8,I8,I8,I8,I8,I8,I8
__device__ unsigned g_g2p[BATCH * KTGT] = { I64, I64, I64, I64 }; // +inf bits
__device__ int      g_cnt[BATCH];
__device__ float    g_dist[BATCH], g_p2g[BATCH], g_sep[BATCH];
__device__ unsigned g_ticket;                                      // zero-init

// ------------- f32x2 packed-math helpers (Blackwell FFMA2 path) -----------
__device__ __forceinline__ u64 pk2(float a, float b) {
    u64 d; asm("mov.b64 %0, {%1, %2};" : "=l"(d) : "f"(a), "f"(b)); return d;
}
__device__ __forceinline__ void upk2(float& a, float& b, u64 d) {
    asm("mov.b64 {%0, %1}, %2;" : "=f"(a), "=f"(b) : "l"(d));
}
__device__ __forceinline__ u64 add2(u64 a, u64 b) {
    u64 d; asm("add.rn.f32x2 %0, %1, %2;" : "=l"(d) : "l"(a), "l"(b)); return d;
}
__device__ __forceinline__ u64 fma2(u64 a, u64 b, u64 c) {
    u64 d; asm("fma.rn.f32x2 %0, %1, %2, %3;" : "=l"(d) : "l"(a), "l"(b), "l"(c)); return d;
}
__device__ __forceinline__ float half_of(u64 d, int h) {
    float a, b; upk2(a, b, d); return h ? b : a;
}

struct __align__(16) Smem {
    u64      s_tp[KTGT * 4];   // (-2tx,-2ty,-2tz,|t|^2) duplicated f32x2
    float    s_d0[TPB * L];
    float    s_red[12];        // 3 sums x 4 warps
    float    s_fin[BATCH];
    int      s_cnt;
    unsigned s_last;
};

// ------------- one tile per block; HW scheduler balances the tail ----------
__global__ void __launch_bounds__(TPB, 8) k_main(
    const float* __restrict__ lC, const float* __restrict__ lF,
    const float* __restrict__ tC, const int* __restrict__ tF,
    const int* __restrict__ classes, int nclass, int N, int ntx,
    float* __restrict__ out)
{
    __shared__ Smem sm;
    const int tid  = threadIdx.x;
    const int lane = tid & 31;

    const int tile = blockIdx.x;
    const int b    = tile / ntx;
    const int base = (tile - b * ntx) * TILE;

    // ---- landmark loads + P-form precompute (LDGs overlap compaction)
    u64 cx2[2], cy2[2], cz2[2], c22[2], px2[2], py2[2], pz2[2], p22[2];
    #pragma unroll
    for (int p = 0; p < 2; p++) {
        float cc[2][3], pp[2][3], c2h[2], p2h[2];
        #pragma unroll
        for (int h = 0; h < 2; h++) {
            int i = 2 * p + h;
            int n = base + tid + i * TPB;
            float d0v = 0.f;
            if (n < N) {
                const float* pc = lC + ((size_t)b * N + n) * 3;
                cc[h][0] = pc[0]; cc[h][1] = pc[1]; cc[h][2] = pc[2];
                float4 f = reinterpret_cast<const float4*>(lF)[(size_t)b * N + n];
                d0v = f.x;
                pp[h][0] = cc[h][0] + f.y;
                pp[h][1] = cc[h][1] + f.z;
                pp[h][2] = cc[h][2] + f.w;
            } else {
                cc[h][0] = 1e18f; cc[h][1] = 0.f; cc[h][2] = 0.f;
                pp[h][0] = 1e18f; pp[h][1] = 0.f; pp[h][2] = 0.f;
            }
            sm.s_d0[tid + i * TPB] = d0v;
            c2h[h] = fmaf(cc[h][0], cc[h][0], fmaf(cc[h][1], cc[h][1], cc[h][2] * cc[h][2]));
            p2h[h] = fmaf(pp[h][0], pp[h][0], fmaf(pp[h][1], pp[h][1], pp[h][2] * pp[h][2]));
        }
        cx2[p] = pk2(cc[0][0], cc[1][0]);
        cy2[p] = pk2(cc[0][1], cc[1][1]);
        cz2[p] = pk2(cc[0][2], cc[1][2]);
        c22[p] = pk2(c2h[0],   c2h[1]);
        px2[p] = pk2(pp[0][0], pp[1][0]);
        py2[p] = pk2(pp[0][1], pp[1][1]);
        pz2[p] = pk2(pp[0][2], pp[1][2]);
        p22[p] = pk2(p2h[0],   p2h[1]);
    }

    // ---- per-tile target compaction (warp 0): (-2t, |t|^2) duplicated
    if (tid < 32) {
        int cnt = 0;
        #pragma unroll
        for (int half = 0; half < 2; half++) {
            int k = lane + 32 * half;
            int c = tF[b * KTGT + k];
            bool m = false;
            for (int j = 0; j < nclass; j++) m |= (c == __ldg(&classes[j]));
            unsigned bal = __ballot_sync(0xffffffffu, m);
            int pos = cnt + __popc(bal & ((1u << lane) - 1u));
            if (m) {
                const float* p = tC + (b * KTGT + k) * 3;
                float x = p[0], y = p[1], z = p[2];
                float t2 = fmaf(x, x, fmaf(y, y, z * z));
                sm.s_tp[pos * 4 + 0] = pk2(-2.f * x, -2.f * x);
                sm.s_tp[pos * 4 + 1] = pk2(-2.f * y, -2.f * y);
                sm.s_tp[pos * 4 + 2] = pk2(-2.f * z, -2.f * z);
                sm.s_tp[pos * 4 + 3] = pk2(t2, t2);
            }
            cnt += __popc(bal);
        }
        if (lane == 0) { sm.s_cnt = cnt; g_cnt[b] = cnt; }
    }
    __syncthreads();
    const int cnt = sm.s_cnt;

    // ---- trackers (identical to R14)
    unsigned bk[L], sk[L];
    float    lmin[L];
    #pragma unroll
    for (int i = 0; i < L; i++) { bk[i] = 0xFFFFFFFFu; sk[i] = 0xFFFFFFFFu; lmin[i] = 3e38f; }
    unsigned r0 = 0x7f800000u, r1 = 0x7f800000u;

    auto body = [&](int k) -> unsigned {
        const ulonglong2* tp = reinterpret_cast<const ulonglong2*>(sm.s_tp + k * 4);
        ulonglong2 tA = tp[0];            // .x=-2tx .y=-2ty
        ulonglong2 tB = tp[1];            // .x=-2tz .y=|t|^2
        float m4a, m4b;
        #pragma unroll
        for (int p = 0; p < 2; p++) {
            u64 pd2 = fma2(cx2[p], tA.x, fma2(cy2[p], tA.y,
                      fma2(cz2[p], tB.x, add2(c22[p], tB.y))));
            u64 l2  = fma2(px2[p], tA.x, fma2(py2[p], tA.y,
                      fma2(pz2[p], tB.x, add2(p22[p], tB.y))));
            float pa, pb, la, lb;
            upk2(pa, pb, pd2);
            upk2(la, lb, l2);
            lmin[2*p]   = fminf(lmin[2*p],   la);
            lmin[2*p+1] = fminf(lmin[2*p+1], lb);
            float mm = fminf(la, lb);
            if (p == 0) m4a = mm; else m4b = mm;
            unsigned ka = (__float_as_uint(pa) & 0xFFFFFFC0u) | (unsigned)k;
            unsigned kb = (__float_as_uint(pb) & 0xFFFFFFC0u) | (unsigned)k;
            unsigned ta = max(ka, bk[2*p]);
            sk[2*p]   = min(sk[2*p], ta);
            bk[2*p]   = min(bk[2*p], ka);
            unsigned tb = max(kb, bk[2*p+1]);
            sk[2*p+1] = min(sk[2*p+1], tb);
            bk[2*p+1] = min(bk[2*p+1], kb);
        }
        return __reduce_min_sync(0xffffffffu, __float_as_uint(fminf(m4a, m4b)));
    };

    // REDUX consumption delayed one iteration to hide latency (R14 scheme)
    int kend0 = (cnt < 32) ? cnt : 32;
    {
        unsigned rp = 0; int kp = 99;
        #pragma unroll 2
        for (int k = 0; k < kend0; k++) {
            unsigned red = body(k);
            if (lane == kp) r0 = min(r0, rp);
            rp = red; kp = k;
        }
        if (lane == kp) r0 = min(r0, rp);
    }
    {
        unsigned rp = 0; int kp = 99;
        #pragma unroll 2
        for (int k = kend0; k < cnt; k++) {
            unsigned red = body(k);
            if (lane == kp) r1 = min(r1, rp);
            rp = red; kp = k - 32;
        }
        if (lane == kp) r1 = min(r1, rp);
    }

    // per-warp g2p mins straight to global (return unused -> REDG)
    atomicMin(&g_g2p[b * KTGT + lane],      r0);
    atomicMin(&g_g2p[b * KTGT + 32 + lane], r1);

    // ---- post-loop per-landmark terms
    auto ld2_at = [&](int i, int kk) -> float {
        int p = i >> 1, h = i & 1;
        float ntx_ = half_of(sm.s_tp[kk * 4 + 0], 0);
        float nty_ = half_of(sm.s_tp[kk * 4 + 1], 0);
        float ntz_ = half_of(sm.s_tp[kk * 4 + 2], 0);
        float tt2  = half_of(sm.s_tp[kk * 4 + 3], 0);
        float l = fmaf(half_of(px2[p], h), ntx_,
                  fmaf(half_of(py2[p], h), nty_,
                  fmaf(half_of(pz2[p], h), ntz_, half_of(p22[p], h) + tt2)));
        return fmaxf(l, 0.f);
    };

    float dl = 0.f, p2g2 = 0.f, sep = 0.f;
    #pragma unroll
    for (int i = 0; i < L; i++) {
        bool  valid = (base + tid + i * TPB) < N;
        float d0v   = sm.s_d0[tid + i * TPB];
        float pd2b  = __uint_as_float(bk[i] & 0xFFFFFFC0u);
        float mind  = sqrtf(pd2b);               // huge if cnt==0 -> fminf picks 0.2
        bool  pm    = mind < 0.1f;
        float tgt   = fminf(mind, 0.2f);
        float diff  = d0v - tgt;
        float ad    = fabsf(diff);
        float h     = (ad < 1.f) ? 0.5f * diff * diff : (ad - 0.5f);
        dl += valid ? h : 0.f;
        if (pm) {
            float l1 = ld2_at(i, (int)(bk[i] & 63u));
            float l2 = ld2_at(i, (int)(sk[i] & 63u));
            p2g2 += fmaxf(lmin[i], 0.f);
            sep  += sqrtf(__fdividef(l1, l2));
        }
    }

    #pragma unroll
    for (int o = 16; o > 0; o >>= 1) {
        dl   += __shfl_down_sync(0xffffffffu, dl,   o);
        p2g2 += __shfl_down_sync(0xffffffffu, p2g2, o);
        sep  += __shfl_down_sync(0xffffffffu, sep,  o);
    }
    int wid = tid >> 5;                          // 0..3
    if (lane == 0) { sm.s_red[wid] = dl; sm.s_red[4 + wid] = p2g2; sm.s_red[8 + wid] = sep; }
    __syncthreads();
    if (tid == 0) {
        float a0 = 0.f, a1 = 0.f, a2 = 0.f;
        #pragma unroll
        for (int i = 0; i < 4; i++) { a0 += sm.s_red[i]; a1 += sm.s_red[4 + i]; a2 += sm.s_red[8 + i]; }
        atomicAdd(&g_dist[b], a0);
        atomicAdd(&g_p2g[b],  a1);
        atomicAdd(&g_sep[b],  a2);
    }

    // ---- last-block finalize + restore pristine scratch for next replay
    __threadfence();
    if (tid == 0) sm.s_last = atomicAdd(&g_ticket, 1u);
    __syncthreads();
    if (sm.s_last == gridDim.x - 1u) {
        // warp w (0..3) sums batch w's g2p mins (64 entries, 2 per lane)
        int w = tid >> 5;
        int cb = g_cnt[w];
        float va = (lane      < cb) ? __uint_as_float(g_g2p[w * KTGT + lane])      : 0.f;
        float vb = (lane + 32 < cb) ? __uint_as_float(g_g2p[w * KTGT + 32 + lane]) : 0.f;
        float v = va + vb;
        #pragma unroll
        for (int o = 16; o > 0; o >>= 1) v += __shfl_down_sync(0xffffffffu, v, o);
        if (lane == 0) sm.s_fin[w] = v;
        __syncthreads();
        if (tid == 0) {
            float acc = 0.f;
            #pragma unroll
            for (int bb = 0; bb < BATCH; bb++) {
                acc += 0.05f * g_dist[bb]
                     + 0.05f * (g_p2g[bb] + sm.s_fin[bb])
                     + 0.0005f * ((g_cnt[bb] >= 2) ? g_sep[bb] : 0.f);
                g_dist[bb] = 0.f; g_p2g[bb] = 0.f; g_sep[bb] = 0.f;
            }
            out[0] = acc * (1.f / BATCH);
            g_ticket = 0;
        }
        g_g2p[tid]       = 0x7f800000u;   // restore all 256 entries (128 threads x2)
        g_g2p[tid + 128] = 0x7f800000u;
    }
}

// ---------------- launch ---------------------------------------------------
extern "C" void kernel_launch(void* const* d_in, const int* in_sizes, int n_in,
                              void* d_out, int out_size)
{
    const float* lC      = (const float*)d_in[0];
    const float* lF      = (const float*)d_in[1];
    const float* tC      = (const float*)d_in[2];
    const int*   tF      = (const int*)d_in[3];
    const int*   classes = (const int*)d_in[4];
    int nclass = in_sizes[4];
    int N      = in_sizes[0] / (BATCH * 3);
    int ntx    = (N + TILE - 1) / TILE;
    int ntiles = ntx * BATCH;

    // plain launch: one tile per block, hardware work-steals the tail wave
    k_main<<<ntiles, TPB>>>(lC, lF, tC, tF, classes, nclass, N, ntx, (float*)d_out);
}

// round 17
// speedup vs baseline: 1.6154x; 1.1096x over previous
#include <cuda_runtime.h>

#define BATCH 4
#define KTGT  64
#define L     4                 // landmarks per thread (2 f32x2 pairs)
#define TPB   128               // validated optimum (R14)
#define TILE  (TPB * L)         // 512

typedef unsigned long long u64;

// ------------- statically-initialized device scratch (no allocs) ----------
#define I8  0x7f800000u,0x7f800000u,0x7f800000u,0x7f800000u,0x7f800000u,0x7f800000u,0x7f800000u,0x7f800000u
#define I64 I8,I8,I8,I8,I8,I8,I8,I8
__device__ unsigned g_g2p[BATCH * KTGT] = { I64, I64, I64, I64 }; // +inf bits
__device__ int      g_cnt[BATCH];
__device__ float    g_dist[BATCH], g_p2g[BATCH], g_sep[BATCH];
__device__ unsigned g_ticket;                                      // zero-init

// ------------- f32x2 packed-math helpers (Blackwell FFMA2 path) -----------
__device__ __forceinline__ u64 pk2(float a, float b) {
    u64 d; asm("mov.b64 %0, {%1, %2};" : "=l"(d) : "f"(a), "f"(b)); return d;
}
__device__ __forceinline__ void upk2(float& a, float& b, u64 d) {
    asm("mov.b64 {%0, %1}, %2;" : "=f"(a), "=f"(b) : "l"(d));
}
__device__ __forceinline__ u64 add2(u64 a, u64 b) {
    u64 d; asm("add.rn.f32x2 %0, %1, %2;" : "=l"(d) : "l"(a), "l"(b)); return d;
}
__device__ __forceinline__ u64 fma2(u64 a, u64 b, u64 c) {
    u64 d; asm("fma.rn.f32x2 %0, %1, %2, %3;" : "=l"(d) : "l"(a), "l"(b), "l"(c)); return d;
}
__device__ __forceinline__ float half_of(u64 d, int h) {
    float a, b; upk2(a, b, d); return h ? b : a;
}

struct __align__(16) Smem {
    u64      s_tp[KTGT * 4];   // (-2tx,-2ty,-2tz,|t|^2) duplicated f32x2
    float    s_d0[TPB * L];
    float    s_red[12];        // 3 sums x 4 warps
    float    s_fin[BATCH];
    int      s_cnt;
    unsigned s_last;
};

// ---------------- persistent fused kernel (R14 + unroll 4) -----------------
__global__ void __launch_bounds__(TPB, 8) k_main(
    const float* __restrict__ lC, const float* __restrict__ lF,
    const float* __restrict__ tC, const int* __restrict__ tF,
    const int* __restrict__ classes, int nclass, int N, int ntx,
    float* __restrict__ out)
{
    __shared__ Smem sm;
    const int tid  = threadIdx.x;
    const int lane = tid & 31;
    const int ntiles = ntx * BATCH;

    for (int tile = blockIdx.x; tile < ntiles; tile += gridDim.x) {
        const int b    = tile / ntx;
        const int base = (tile - b * ntx) * TILE;

        __syncthreads();   // previous tile fully consumed smem

        // ---- landmark loads + P-form precompute (LDGs overlap compaction)
        u64 cx2[2], cy2[2], cz2[2], c22[2], px2[2], py2[2], pz2[2], p22[2];
        #pragma unroll
        for (int p = 0; p < 2; p++) {
            float cc[2][3], pp[2][3], c2h[2], p2h[2];
            #pragma unroll
            for (int h = 0; h < 2; h++) {
                int i = 2 * p + h;
                int n = base + tid + i * TPB;
                float d0v = 0.f;
                if (n < N) {
                    const float* pc = lC + ((size_t)b * N + n) * 3;
                    cc[h][0] = pc[0]; cc[h][1] = pc[1]; cc[h][2] = pc[2];
                    float4 f = reinterpret_cast<const float4*>(lF)[(size_t)b * N + n];
                    d0v = f.x;
                    pp[h][0] = cc[h][0] + f.y;
                    pp[h][1] = cc[h][1] + f.z;
                    pp[h][2] = cc[h][2] + f.w;
                } else {
                    cc[h][0] = 1e18f; cc[h][1] = 0.f; cc[h][2] = 0.f;
                    pp[h][0] = 1e18f; pp[h][1] = 0.f; pp[h][2] = 0.f;
                }
                sm.s_d0[tid + i * TPB] = d0v;
                c2h[h] = fmaf(cc[h][0], cc[h][0], fmaf(cc[h][1], cc[h][1], cc[h][2] * cc[h][2]));
                p2h[h] = fmaf(pp[h][0], pp[h][0], fmaf(pp[h][1], pp[h][1], pp[h][2] * pp[h][2]));
            }
            cx2[p] = pk2(cc[0][0], cc[1][0]);
            cy2[p] = pk2(cc[0][1], cc[1][1]);
            cz2[p] = pk2(cc[0][2], cc[1][2]);
            c22[p] = pk2(c2h[0],   c2h[1]);
            px2[p] = pk2(pp[0][0], pp[1][0]);
            py2[p] = pk2(pp[0][1], pp[1][1]);
            pz2[p] = pk2(pp[0][2], pp[1][2]);
            p22[p] = pk2(p2h[0],   p2h[1]);
        }

        // ---- per-tile target compaction (warp 0): (-2t, |t|^2) duplicated
        if (tid < 32) {
            int cnt = 0;
            #pragma unroll
            for (int half = 0; half < 2; half++) {
                int k = lane + 32 * half;
                int c = tF[b * KTGT + k];
                bool m = false;
                for (int j = 0; j < nclass; j++) m |= (c == __ldg(&classes[j]));
                unsigned bal = __ballot_sync(0xffffffffu, m);
                int pos = cnt + __popc(bal & ((1u << lane) - 1u));
                if (m) {
                    const float* p = tC + (b * KTGT + k) * 3;
                    float x = p[0], y = p[1], z = p[2];
                    float t2 = fmaf(x, x, fmaf(y, y, z * z));
                    sm.s_tp[pos * 4 + 0] = pk2(-2.f * x, -2.f * x);
                    sm.s_tp[pos * 4 + 1] = pk2(-2.f * y, -2.f * y);
                    sm.s_tp[pos * 4 + 2] = pk2(-2.f * z, -2.f * z);
                    sm.s_tp[pos * 4 + 3] = pk2(t2, t2);
                }
                cnt += __popc(bal);
            }
            if (lane == 0) { sm.s_cnt = cnt; g_cnt[b] = cnt; }
        }
        __syncthreads();
        const int cnt = sm.s_cnt;

        // ---- trackers (identical to R14)
        unsigned bk[L], sk[L];
        float    lmin[L];
        #pragma unroll
        for (int i = 0; i < L; i++) { bk[i] = 0xFFFFFFFFu; sk[i] = 0xFFFFFFFFu; lmin[i] = 3e38f; }
        unsigned r0 = 0x7f800000u, r1 = 0x7f800000u;

        auto body = [&](int k) -> unsigned {
            const ulonglong2* tp = reinterpret_cast<const ulonglong2*>(sm.s_tp + k * 4);
            ulonglong2 tA = tp[0];            // .x=-2tx .y=-2ty
            ulonglong2 tB = tp[1];            // .x=-2tz .y=|t|^2
            float m4a, m4b;
            #pragma unroll
            for (int p = 0; p < 2; p++) {
                u64 pd2 = fma2(cx2[p], tA.x, fma2(cy2[p], tA.y,
                          fma2(cz2[p], tB.x, add2(c22[p], tB.y))));
                u64 l2  = fma2(px2[p], tA.x, fma2(py2[p], tA.y,
                          fma2(pz2[p], tB.x, add2(p22[p], tB.y))));
                float pa, pb, la, lb;
                upk2(pa, pb, pd2);
                upk2(la, lb, l2);
                lmin[2*p]   = fminf(lmin[2*p],   la);
                lmin[2*p+1] = fminf(lmin[2*p+1], lb);
                float mm = fminf(la, lb);
                if (p == 0) m4a = mm; else m4b = mm;
                unsigned ka = (__float_as_uint(pa) & 0xFFFFFFC0u) | (unsigned)k;
                unsigned kb = (__float_as_uint(pb) & 0xFFFFFFC0u) | (unsigned)k;
                unsigned ta = max(ka, bk[2*p]);
                sk[2*p]   = min(sk[2*p], ta);
                bk[2*p]   = min(bk[2*p], ka);
                unsigned tb = max(kb, bk[2*p+1]);
                sk[2*p+1] = min(sk[2*p+1], tb);
                bk[2*p+1] = min(bk[2*p+1], kb);
            }
            return __reduce_min_sync(0xffffffffu, __float_as_uint(fminf(m4a, m4b)));
        };

        // REDUX consumption delayed one iteration; unroll 4 for ILP coverage
        int kend0 = (cnt < 32) ? cnt : 32;
        {
            unsigned rp = 0; int kp = 99;
            #pragma unroll 4
            for (int k = 0; k < kend0; k++) {
                unsigned red = body(k);
                if (lane == kp) r0 = min(r0, rp);
                rp = red; kp = k;
            }
            if (lane == kp) r0 = min(r0, rp);
        }
        {
            unsigned rp = 0; int kp = 99;
            #pragma unroll 4
            for (int k = kend0; k < cnt; k++) {
                unsigned red = body(k);
                if (lane == kp) r1 = min(r1, rp);
                rp = red; kp = k - 32;
            }
            if (lane == kp) r1 = min(r1, rp);
        }

        // per-warp g2p mins straight to global (return unused -> REDG)
        atomicMin(&g_g2p[b * KTGT + lane],      r0);
        atomicMin(&g_g2p[b * KTGT + 32 + lane], r1);

        // ---- post-loop per-landmark terms
        auto ld2_at = [&](int i, int kk) -> float {
            int p = i >> 1, h = i & 1;
            float ntx_ = half_of(sm.s_tp[kk * 4 + 0], 0);
            float nty_ = half_of(sm.s_tp[kk * 4 + 1], 0);
            float ntz_ = half_of(sm.s_tp[kk * 4 + 2], 0);
            float tt2  = half_of(sm.s_tp[kk * 4 + 3], 0);
            float l = fmaf(half_of(px2[p], h), ntx_,
                      fmaf(half_of(py2[p], h), nty_,
                      fmaf(half_of(pz2[p], h), ntz_, half_of(p22[p], h) + tt2)));
            return fmaxf(l, 0.f);
        };

        float dl = 0.f, p2g2 = 0.f, sep = 0.f;
        #pragma unroll
        for (int i = 0; i < L; i++) {
            bool  valid = (base + tid + i * TPB) < N;
            float d0v   = sm.s_d0[tid + i * TPB];
            float pd2b  = __uint_as_float(bk[i] & 0xFFFFFFC0u);
            float mind  = sqrtf(pd2b);               // huge if cnt==0 -> fminf picks 0.2
            bool  pm    = mind < 0.1f;
            float tgt   = fminf(mind, 0.2f);
            float diff  = d0v - tgt;
            float ad    = fabsf(diff);
            float h     = (ad < 1.f) ? 0.5f * diff * diff : (ad - 0.5f);
            dl += valid ? h : 0.f;
            if (pm) {
                float l1 = ld2_at(i, (int)(bk[i] & 63u));
                float l2 = ld2_at(i, (int)(sk[i] & 63u));
                p2g2 += fmaxf(lmin[i], 0.f);
                sep  += sqrtf(__fdividef(l1, l2));
            }
        }

        #pragma unroll
        for (int o = 16; o > 0; o >>= 1) {
            dl   += __shfl_down_sync(0xffffffffu, dl,   o);
            p2g2 += __shfl_down_sync(0xffffffffu, p2g2, o);
            sep  += __shfl_down_sync(0xffffffffu, sep,  o);
        }
        int wid = tid >> 5;                          // 0..3
        if (lane == 0) { sm.s_red[wid] = dl; sm.s_red[4 + wid] = p2g2; sm.s_red[8 + wid] = sep; }
        __syncthreads();
        if (tid == 0) {
            float a0 = 0.f, a1 = 0.f, a2 = 0.f;
            #pragma unroll
            for (int i = 0; i < 4; i++) { a0 += sm.s_red[i]; a1 += sm.s_red[4 + i]; a2 += sm.s_red[8 + i]; }
            atomicAdd(&g_dist[b], a0);
            atomicAdd(&g_p2g[b],  a1);
            atomicAdd(&g_sep[b],  a2);
        }
    }

    // ---- last-block finalize + restore pristine scratch for next replay
    __threadfence();
    if (tid == 0) sm.s_last = atomicAdd(&g_ticket, 1u);
    __syncthreads();
    if (sm.s_last == gridDim.x - 1u) {
        // warp w (0..3) sums batch w's g2p mins (64 entries, 2 per lane)
        int w = tid >> 5;
        int cb = g_cnt[w];
        float va = (lane      < cb) ? __uint_as_float(g_g2p[w * KTGT + lane])      : 0.f;
        float vb = (lane + 32 < cb) ? __uint_as_float(g_g2p[w * KTGT + 32 + lane]) : 0.f;
        float v = va + vb;
        #pragma unroll
        for (int o = 16; o > 0; o >>= 1) v += __shfl_down_sync(0xffffffffu, v, o);
        if (lane == 0) sm.s_fin[w] = v;
        __syncthreads();
        if (tid == 0) {
            float acc = 0.f;
            #pragma unroll
            for (int bb = 0; bb < BATCH; bb++) {
                acc += 0.05f * g_dist[bb]
                     + 0.05f * (g_p2g[bb] + sm.s_fin[bb])
                     + 0.0005f * ((g_cnt[bb] >= 2) ? g_sep[bb] : 0.f);
                g_dist[bb] = 0.f; g_p2g[bb] = 0.f; g_sep[bb] = 0.f;
            }
            out[0] = acc * (1.f / BATCH);
            g_ticket = 0;
        }
        g_g2p[tid]       = 0x7f800000u;   // restore all 256 entries (128 threads x2)
        g_g2p[tid + 128] = 0x7f800000u;
    }
}

// ---------------- launch ---------------------------------------------------
extern "C" void kernel_launch(void* const* d_in, const int* in_sizes, int n_in,
                              void* d_out, int out_size)
{
    const float* lC      = (const float*)d_in[0];
    const float* lF      = (const float*)d_in[1];
    const float* tC      = (const float*)d_in[2];
    const int*   tF      = (const int*)d_in[3];
    const int*   classes = (const int*)d_in[4];
    int nclass = in_sizes[4];
    int N      = in_sizes[0] / (BATCH * 3);
    int ntx    = (N + TILE - 1) / TILE;
    int ntiles = ntx * BATCH;

    // capture-time host queries (no stream work, graph-legal)
    int dev = 0; cudaGetDevice(&dev);
    int sms = 148;
    cudaDeviceGetAttribute(&sms, cudaDevAttrMultiProcessorCount, dev);
    int bps = 0;
    cudaOccupancyMaxActiveBlocksPerMultiprocessor(&bps, k_main, TPB, 0);
    if (bps < 1) bps = 1;
    int grid = sms * bps;
    if (grid > ntiles) grid = ntiles;

    k_main<<<grid, TPB>>>(lC, lF, tC, tF, classes, nclass, N, ntx, (float*)d_out);
}